// round 3
// baseline (speedup 1.0000x reference)
#include <cuda_runtime.h>

#define N_NODES 100000
#define IN_CH   128
#define OUT_TOT 128   // HEADS * OUT_CH = 4 * 32
#define N_EDGES 1600000

#define BM 128
#define BN 128
#define BK 16
#define TM 8
#define TN 8
#define NT 256

// Scratch: per-node "has at least one incoming edge" flag.
__device__ unsigned char g_mask[N_NODES];

__global__ void mask_zero_kernel() {
    int i = blockIdx.x * blockDim.x + threadIdx.x;
    if (i < N_NODES) g_mask[i] = 0;
}

// NOTE: edge_index is int32 (JAX without x64 silently downcasts int64->int32).
__global__ void mask_scatter_kernel(const int* __restrict__ col) {
    int i = blockIdx.x * blockDim.x + threadIdx.x;
    if (i < N_EDGES) {
        unsigned c = (unsigned)col[i];
        if (c < N_NODES) g_mask[c] = 1;   // benign same-value race
    }
}

// C[n,:] = mask[n] ? A[n,:] @ B : 0
// A: [N_NODES, 128] row-major, B: [128, 128] row-major, C: [N_NODES, 128]
__global__ __launch_bounds__(NT) void gat_gemm_kernel(
    const float* __restrict__ A, const float* __restrict__ B,
    float* __restrict__ C)
{
    __shared__ float As[BK][BM + 4];   // +4 pad: kill STS bank conflicts, keep 16B align
    __shared__ float Bs[BK][BN];

    const int tid = threadIdx.x;
    const int tx = tid & 15;    // output column group (TN=8 wide)
    const int ty = tid >> 4;    // output row group (TM=8 tall)
    const int row0 = blockIdx.x * BM;

    float acc[TM][TN];
#pragma unroll
    for (int i = 0; i < TM; i++)
#pragma unroll
        for (int j = 0; j < TN; j++) acc[i][j] = 0.f;

    for (int kk = 0; kk < IN_CH; kk += BK) {
        // ---- Load A tile (BM x BK), store transposed As[k][m] ----
        // 512 float4 loads, 2 per thread.
#pragma unroll
        for (int l = 0; l < 2; l++) {
            int idx = tid + l * NT;      // 0..511
            int r   = idx >> 2;          // 0..127 (tile row)
            int c4  = idx & 3;           // 0..3   (float4 within k-slice)
            int gr  = row0 + r;
            float4 v = make_float4(0.f, 0.f, 0.f, 0.f);
            if (gr < N_NODES)
                v = *reinterpret_cast<const float4*>(&A[(long)gr * IN_CH + kk + c4 * 4]);
            As[c4 * 4 + 0][r] = v.x;
            As[c4 * 4 + 1][r] = v.y;
            As[c4 * 4 + 2][r] = v.z;
            As[c4 * 4 + 3][r] = v.w;
        }
        // ---- Load B tile (BK x BN) directly ----
#pragma unroll
        for (int l = 0; l < 2; l++) {
            int idx = tid + l * NT;      // 0..511
            int r   = idx >> 5;          // 0..15
            int c4  = idx & 31;          // 0..31
            float4 v = *reinterpret_cast<const float4*>(&B[(kk + r) * OUT_TOT + c4 * 4]);
            *reinterpret_cast<float4*>(&Bs[r][c4 * 4]) = v;
        }
        __syncthreads();

        // ---- 8x8 register-blocked FMA ----
#pragma unroll
        for (int k = 0; k < BK; k++) {
            float a[TM], b[TN];
#pragma unroll
            for (int i = 0; i < TM; i += 4)
                *reinterpret_cast<float4*>(&a[i]) =
                    *reinterpret_cast<const float4*>(&As[k][ty * TM + i]);
#pragma unroll
            for (int j = 0; j < TN; j += 4)
                *reinterpret_cast<float4*>(&b[j]) =
                    *reinterpret_cast<const float4*>(&Bs[k][tx * TN + j]);
#pragma unroll
            for (int i = 0; i < TM; i++)
#pragma unroll
                for (int j = 0; j < TN; j++)
                    acc[i][j] = fmaf(a[i], b[j], acc[i][j]);
        }
        __syncthreads();
    }

    // ---- Epilogue: apply indegree mask, vectorized stores ----
#pragma unroll
    for (int i = 0; i < TM; i++) {
        int r = row0 + ty * TM + i;
        if (r < N_NODES) {
            float m = g_mask[r] ? 1.0f : 0.0f;
            float4 v0 = make_float4(acc[i][0] * m, acc[i][1] * m,
                                    acc[i][2] * m, acc[i][3] * m);
            float4 v1 = make_float4(acc[i][4] * m, acc[i][5] * m,
                                    acc[i][6] * m, acc[i][7] * m);
            float* cp = &C[(long)r * OUT_TOT + tx * TN];
            *reinterpret_cast<float4*>(cp)     = v0;
            *reinterpret_cast<float4*>(cp + 4) = v1;
        }
    }
}

extern "C" void kernel_launch(void* const* d_in, const int* in_sizes, int n_in,
                              void* d_out, int out_size)
{
    const float* x = (const float*)d_in[0];          // [100000, 128]
    const float* w = (const float*)d_in[1];          // [128, 128]
    // d_in[2] = att — mathematically irrelevant to the output (softmax weights
    // sum to 1 per destination segment and multiply that segment's own features)
    const int* edge_index = (const int*)d_in[3];     // [2, 1600000] int32
    const int* col = edge_index + N_EDGES;           // edge_index[1]
    float* out = (float*)d_out;                      // [100000, 128]

    mask_zero_kernel<<<(N_NODES + 255) / 256, 256>>>();
    mask_scatter_kernel<<<(N_EDGES + 255) / 256, 256>>>(col);
    gat_gemm_kernel<<<(N_NODES + BM - 1) / BM, NT>>>(x, w, out);
}